// round 15
// baseline (speedup 1.0000x reference)
#include <cuda_runtime.h>
#include <cuda_fp16.h>
#include <cstdint>

#define NB 16
#define CD 256
#define HW 4096
#define KA 512
#define ROWS (NB*HW)   // 65536

// ---------------- scratch (__device__ globals; no allocations) ----------------
__device__ __align__(16) __half g_A0[(size_t)ROWS * KA];             // 64 MB (fp16)
__device__ __align__(16) __half g_Xf[(size_t)ROWS * CD];             // X^T*invnorm fp16 [n][hw][c]
__device__ __align__(16) __half g_Sfj[(size_t)NB*KA*CD];             // S fp16 [n][j][c]
__device__ __align__(16) float  g_Scf[(size_t)NB*CD*KA];             // S fp32 [n][c][j]
__device__ __align__(16) __half g_Sck[(size_t)NB*CD*KA];             // S*c fp16 [n][c][j]
__device__ float g_invnorm[ROWS];
__device__ float g_dinv[ROWS];
__device__ float g_colsum[KA];
__device__ float g_cvec[KA];

// ---------------- helpers ----------------
__device__ __forceinline__ uint32_t smem_u32(const void* p) {
    uint32_t a;
    asm("{ .reg .u64 t; cvta.to.shared.u64 t, %1; cvt.u32.u64 %0, t; }" : "=r"(a) : "l"(p));
    return a;
}
__device__ __forceinline__ uint32_t swz(uint32_t o) { return o ^ ((o >> 3) & 0x70); }
__device__ __forceinline__ void ldm4(uint32_t addr, uint32_t r[4]) {
    asm volatile("ldmatrix.sync.aligned.m8n8.x4.shared.b16 {%0,%1,%2,%3}, [%4];"
        : "=r"(r[0]), "=r"(r[1]), "=r"(r[2]), "=r"(r[3]) : "r"(addr));
}
__device__ __forceinline__ void mma_hf(float c[4], const uint32_t a[4],
                                       uint32_t b0, uint32_t b1) {
    asm volatile("mma.sync.aligned.m16n8k16.row.col.f32.f16.f16.f32 "
        "{%0,%1,%2,%3}, {%4,%5,%6,%7}, {%8,%9}, {%0,%1,%2,%3};"
        : "+f"(c[0]), "+f"(c[1]), "+f"(c[2]), "+f"(c[3])
        : "r"(a[0]), "r"(a[1]), "r"(a[2]), "r"(a[3]), "r"(b0), "r"(b1));
}
__device__ __forceinline__ uint32_t afrag_addr(uint32_t base, int mbase, int s, int lane) {
    int row = mbase + (lane & 7) + ((lane >> 3) & 1) * 8;
    int unit = 2 * s + (lane >> 4);
    return base + swz((uint32_t)(row * 128 + unit * 16));
}
__device__ __forceinline__ uint32_t bfrag_addr(uint32_t base, int nbase, int s, int lane) {
    int row = nbase + (lane & 7) + ((lane >> 4) & 1) * 8;
    int unit = 2 * s + ((lane >> 3) & 1);
    return base + swz((uint32_t)(row * 128 + unit * 16));
}
#define CPA16(s, g) asm volatile("cp.async.cg.shared.global [%0], [%1], 16;" :: "r"(s), "l"(g))
#define CP_COMMIT() asm volatile("cp.async.commit_group;" ::: "memory")
#define CP_WAIT0()  asm volatile("cp.async.wait_group 0;" ::: "memory")

// register-lean row ops on raw uint4 pairs
__device__ __forceinline__ float dot16_u(const uint4& u0, const uint4& u1, const float* cv) {
    const __half2* h0 = (const __half2*)&u0;
    const __half2* h1 = (const __half2*)&u1;
    float d = 0.0f;
#pragma unroll
    for (int k = 0; k < 4; ++k) {
        float2 f0 = __half22float2(h0[k]);
        float2 f1 = __half22float2(h1[k]);
        d = fmaf(f0.x, cv[2*k],     d); d = fmaf(f0.y, cv[2*k+1],   d);
        d = fmaf(f1.x, cv[8+2*k],   d); d = fmaf(f1.y, cv[8+2*k+1], d);
    }
    return d;
}
__device__ __forceinline__ void acc16_u(float* ca, const uint4& u0, const uint4& u1, float r) {
    const __half2* h0 = (const __half2*)&u0;
    const __half2* h1 = (const __half2*)&u1;
#pragma unroll
    for (int k = 0; k < 4; ++k) {
        float2 f0 = __half22float2(h0[k]);
        float2 f1 = __half22float2(h1[k]);
        ca[2*k]     = fmaf(r, f0.x, ca[2*k]);     ca[2*k+1]   = fmaf(r, f0.y, ca[2*k+1]);
        ca[8+2*k]   = fmaf(r, f1.x, ca[8+2*k]);   ca[8+2*k+1] = fmaf(r, f1.y, ca[8+2*k+1]);
    }
}

// GEMM SMEM: red 512B @0 | stage s @4096+s*32768: AF +0 (16KB), BF +16384 (16KB)
#define G_STG(s) (4096 + (s) * 32768)
#define G_BF 16384
#define G_SMEM (4096 + 65536)   // 69632; 2 CTA/SM

// SK 4-stage full prefetch: cred/cs 2KB @0 | stage s @2048+s*16384
#define SK4_STG(s) (2048 + (s) * 16384)
#define SK4_SMEM (2048 + 65536)  // 67584; 3 CTA/SM

// ---------------- small kernels ----------------

// fused: channel L2 norm + transpose + fp16, Xf = x * invnorm; block(0,0) zeroes colsum
__global__ __launch_bounds__(256) void xtn_kernel(const float* __restrict__ x) {
    __shared__ float t[256][33];
    __shared__ float ps[8][32];
    __shared__ float inv[32];
    int n = blockIdx.y, hw0 = blockIdx.x * 32;
    int tid = threadIdx.x;
    if (blockIdx.x == 0 && blockIdx.y == 0) {
        g_colsum[tid] = 0.0f; g_colsum[tid + 256] = 0.0f;
    }
    int tx = tid & 31, ty = tid >> 5;
    const float* p = x + (size_t)n * CD * HW + hw0 + tx;
#pragma unroll
    for (int cc = 0; cc < 32; ++cc) {
        int c = cc * 8 + ty;
        t[c][tx] = p[(size_t)c * HW];
    }
    __syncthreads();
    float s = 0.f;
#pragma unroll
    for (int k = 0; k < 32; ++k) {
        float v = t[ty * 32 + k][tx];
        s = fmaf(v, v, s);
    }
    ps[ty][tx] = s;
    __syncthreads();
    if (ty == 0) {
        float a = 0.f;
#pragma unroll
        for (int k = 0; k < 8; ++k) a += ps[k][tx];
        float invn = 1.0f / fmaxf(sqrtf(a), 1e-12f);
        inv[tx] = invn;
        g_invnorm[n * HW + hw0 + tx] = invn;
    }
    __syncthreads();
    int c2 = tid & 127, hwp = tid >> 7;
#pragma unroll
    for (int it = 0; it < 16; ++it) {
        int hw = it * 2 + hwp;
        float iv = inv[hw];
        float v0 = t[c2 * 2][hw] * iv;
        float v1 = t[c2 * 2 + 1][hw] * iv;
        *(__half2*)(&g_Xf[((size_t)n * HW + hw0 + hw) * CD + c2 * 2]) =
            __halves2half2(__float2half(v0), __float2half(v1));
    }
}

// merged gather: one scattered read of anchors -> Scf (fp32 [c][j]) + Sfj (fp16 [j][c])
__global__ __launch_bounds__(256) void gather_both(const float* __restrict__ x,
                                                   const int* __restrict__ idx) {
    __shared__ float t[32][129];
    __shared__ int   pos_s[128];
    __shared__ float inv_s[128];
    int n = blockIdx.z, c0 = blockIdx.y * 32, j0 = blockIdx.x * 128;
    int tid = threadIdx.x;
    if (tid < 128) {
        int p = idx[j0 + tid];
        pos_s[tid] = p;
        inv_s[tid] = g_invnorm[n * HW + p];
    }
    __syncthreads();
#pragma unroll
    for (int it = 0; it < 16; ++it) {
        int e = tid + it * 256;
        int c = e >> 7, j = e & 127;
        float v = x[((size_t)(n * CD + c0 + c)) * HW + pos_s[j]] * inv_s[j];
        g_Scf[((size_t)(n * CD + c0 + c)) * KA + j0 + j] = v;
        t[c][j] = v;
    }
    __syncthreads();
#pragma unroll
    for (int it = 0; it < 16; ++it) {
        int e = tid + it * 256;
        int j = e >> 5, c = e & 31;
        g_Sfj[((size_t)(n * KA + j0 + j)) * CD + c0 + c] = __float2half(t[c][j]);
    }
}

// c = (1/colsum) normalized by max; reset colsum (round-10 proven version)
__global__ void recip_kernel() {
    __shared__ float sm[KA];
    int j = threadIdx.x;
    float c = 1.0f / fmaxf(g_colsum[j], 1e-30f);
    sm[j] = c;
    __syncthreads();
    for (int s = 256; s > 0; s >>= 1) {
        if (j < s) sm[j] = fmaxf(sm[j], sm[j + s]);
        __syncthreads();
    }
    g_cvec[j] = c / sm[0];
    g_colsum[j] = 0.0f;
}

// fused Sinkhorn pass: 4-stage FULL prefetch (entire 64KB block of A0 in flight).
__global__ __launch_bounds__(256) void sk_pass() {
    extern __shared__ char smem[];
    uint32_t sb = smem_u32(smem);
    float* cred = (float*)smem;
    int tid = threadIdx.x;
    cred[tid] = 0.0f; cred[tid + 256] = 0.0f;
    int warp = tid >> 5, lane = tid & 31;
    float cv[16];
#pragma unroll
    for (int e = 0; e < 8; ++e) {
        cv[e]     = g_cvec[lane * 8 + e];
        cv[8 + e] = g_cvec[256 + lane * 8 + e];
    }
    float ca[16];
#pragma unroll
    for (int e = 0; e < 16; ++e) ca[e] = 0.0f;

    const char* gbase = (const char*)(g_A0 + (size_t)blockIdx.x * 64 * KA);
    // issue ALL 4 chunks up front (4 commit groups)
#pragma unroll
    for (int ch = 0; ch < 4; ++ch) {
        uint32_t base = sb + SK4_STG(ch);
        const char* g = gbase + (size_t)ch * 16384;
#pragma unroll
        for (int q = 0; q < 4; ++q) {
            uint32_t off = (uint32_t)(tid * 16 + q * 4096);
            CPA16(base + off, g + off);
        }
        CP_COMMIT();
    }
    // consume with descending wait counts
#pragma unroll
    for (int ch = 0; ch < 4; ++ch) {
        if (ch == 0)      asm volatile("cp.async.wait_group 3;" ::: "memory");
        else if (ch == 1) asm volatile("cp.async.wait_group 2;" ::: "memory");
        else if (ch == 2) asm volatile("cp.async.wait_group 1;" ::: "memory");
        else              asm volatile("cp.async.wait_group 0;" ::: "memory");
        __syncthreads();
        const uint4* st = (const uint4*)(smem + SK4_STG(ch));
#pragma unroll
        for (int t = 0; t < 2; ++t) {
            const uint4* row = st + (warp * 2 + t) * 64;
            uint4 u0 = row[lane], u1 = row[lane + 32];
            float d = dot16_u(u0, u1, cv);
#pragma unroll
            for (int s = 16; s > 0; s >>= 1) d += __shfl_xor_sync(0xffffffffu, d, s);
            float r = 1.0f / fmaxf(d, 1e-30f);
            acc16_u(ca, u0, u1, r);
        }
    }
#pragma unroll
    for (int e = 0; e < 8; ++e) {
        atomicAdd(&cred[lane * 8 + e], ca[e]);
        atomicAdd(&cred[256 + lane * 8 + e], ca[8 + e]);
    }
    __syncthreads();
    atomicAdd(&g_colsum[tid], cred[tid]);
    atomicAdd(&g_colsum[tid + 256], cred[tid + 256]);
}

// merged: blocks 0..1023: dinv with 4-stage full prefetch; blocks 1024..: S*c fp16
__global__ __launch_bounds__(256) void prep_recon() {
    extern __shared__ char smem[];
    uint32_t sb = smem_u32(smem);
    float* cs = (float*)smem;   // 512 floats
    int tid = threadIdx.x;
    cs[tid] = g_cvec[tid];
    cs[tid + 256] = g_cvec[tid + 256];
    __syncthreads();

    if (blockIdx.x < 1024) {
        int warp = tid >> 5, lane = tid & 31;
        float cv[16];
#pragma unroll
        for (int e = 0; e < 8; ++e) {
            cv[e] = cs[lane * 8 + e];
            cv[8 + e] = cs[256 + lane * 8 + e];
        }
        const char* gbase = (const char*)(g_A0 + (size_t)blockIdx.x * 64 * KA);
#pragma unroll
        for (int ch = 0; ch < 4; ++ch) {
            uint32_t base = sb + SK4_STG(ch);
            const char* g = gbase + (size_t)ch * 16384;
#pragma unroll
            for (int q = 0; q < 4; ++q) {
                uint32_t off = (uint32_t)(tid * 16 + q * 4096);
                CPA16(base + off, g + off);
            }
            CP_COMMIT();
        }
#pragma unroll
        for (int ch = 0; ch < 4; ++ch) {
            if (ch == 0)      asm volatile("cp.async.wait_group 3;" ::: "memory");
            else if (ch == 1) asm volatile("cp.async.wait_group 2;" ::: "memory");
            else if (ch == 2) asm volatile("cp.async.wait_group 1;" ::: "memory");
            else              asm volatile("cp.async.wait_group 0;" ::: "memory");
            __syncthreads();
            const uint4* st = (const uint4*)(smem + SK4_STG(ch));
#pragma unroll
            for (int t = 0; t < 2; ++t) {
                int r = warp * 2 + t;
                const uint4* row = st + r * 64;
                uint4 u0 = row[lane], u1 = row[lane + 32];
                float d = dot16_u(u0, u1, cv);
#pragma unroll
                for (int s = 16; s > 0; s >>= 1) d += __shfl_xor_sync(0xffffffffu, d, s);
                if (lane == 0)
                    g_dinv[(size_t)blockIdx.x * 64 + ch * 16 + r] = 1.0f / fmaxf(d, 1e-30f);
            }
        }
    } else {
        int t = (blockIdx.x - 1024) * 256 + tid;
        int j = t & (KA - 1);
        g_Sck[t] = __float2half(g_Scf[t] * cs[j]);
    }
}

// ================= score GEMM: fp16 mma, single-sync cp.async pipeline =================
__global__ __launch_bounds__(256, 2) void score_mma() {
    extern __shared__ char smem[];
    uint32_t sb = smem_u32(smem);
    float* colred = (float*)smem;
    int tid = threadIdx.x, lane = tid & 31, w = tid >> 5;
    int n = blockIdx.z, hw0 = blockIdx.x * 128, j0 = blockIdx.y * 128;
    int wm = (w & 3) * 32, wn = (w >> 2) * 64;

    float acc[2][8][4];
#pragma unroll
    for (int a = 0; a < 2; ++a)
#pragma unroll
        for (int b = 0; b < 8; ++b)
#pragma unroll
            for (int c = 0; c < 4; ++c) acc[a][b][c] = 0.0f;

    int crow = tid >> 1, chalf = tid & 1;
    const uint4* aF = (const uint4*)(g_Xf + ((size_t)n * HW + hw0 + crow) * CD);
    const uint4* bF = (const uint4*)(g_Sfj + ((size_t)n * KA + j0 + crow) * CD);

    auto issue = [&](int ch, int st) {
        uint32_t base = sb + G_STG(st);
#pragma unroll
        for (int q = 0; q < 4; ++q) {
            int unit = chalf * 4 + q;
            uint32_t off = swz((uint32_t)(crow * 128 + unit * 16));
            int gi = ch * 8 + unit;
            CPA16(base + off, aF + gi);
            CPA16(base + G_BF + off, bF + gi);
        }
    };

    issue(0, 0); CP_COMMIT();
#pragma unroll 1
    for (int ch = 0; ch < 4; ++ch) {
        CP_WAIT0();
        __syncthreads();
        if (ch + 1 < 4) { issue(ch + 1, (ch + 1) & 1); CP_COMMIT(); }
        uint32_t tb = sb + G_STG(ch & 1);
#pragma unroll
        for (int s = 0; s < 4; ++s) {
            uint32_t af[2][4];
#pragma unroll
            for (int mt = 0; mt < 2; ++mt)
                ldm4(afrag_addr(tb, wm + mt * 16, s, lane), af[mt]);
#pragma unroll
            for (int ng = 0; ng < 4; ++ng) {
                uint32_t bf[4];
                ldm4(bfrag_addr(tb + G_BF, wn + ng * 16, s, lane), bf);
                mma_hf(acc[0][2*ng],   af[0], bf[0], bf[1]);
                mma_hf(acc[1][2*ng],   af[1], bf[0], bf[1]);
                mma_hf(acc[0][2*ng+1], af[0], bf[2], bf[3]);
                mma_hf(acc[1][2*ng+1], af[1], bf[2], bf[3]);
            }
        }
    }

    // epilogue: acc is cosine; exp(acc/T) -> fp16 store + fused first column-sum
    __syncthreads();
    if (tid < 128) colred[tid] = 0.0f;
    __syncthreads();
    const float sc = 1.0f / 0.3f;
    float colp[16];
#pragma unroll
    for (int e = 0; e < 16; ++e) colp[e] = 0.0f;
#pragma unroll
    for (int mt = 0; mt < 2; ++mt) {
        int i0 = n * HW + hw0 + wm + mt * 16 + (lane >> 2);
        int i1 = i0 + 8;
        __half* r0 = g_A0 + (size_t)i0 * KA + j0 + wn + (lane & 3) * 2;
        __half* r1 = g_A0 + (size_t)i1 * KA + j0 + wn + (lane & 3) * 2;
#pragma unroll
        for (int nt = 0; nt < 8; ++nt) {
            __half h0 = __float2half(__expf(acc[mt][nt][0] * sc));
            __half h1 = __float2half(__expf(acc[mt][nt][1] * sc));
            __half h2 = __float2half(__expf(acc[mt][nt][2] * sc));
            __half h3 = __float2half(__expf(acc[mt][nt][3] * sc));
            *(__half2*)(r0 + nt * 8) = __halves2half2(h0, h1);
            *(__half2*)(r1 + nt * 8) = __halves2half2(h2, h3);
            colp[nt * 2]     += __half2float(h0) + __half2float(h2);
            colp[nt * 2 + 1] += __half2float(h1) + __half2float(h3);
        }
    }
#pragma unroll
    for (int nt = 0; nt < 8; ++nt) {
        int cl = wn + (lane & 3) * 2 + nt * 8;
        atomicAdd(&colred[cl], colp[nt * 2]);
        atomicAdd(&colred[cl + 1], colp[nt * 2 + 1]);
    }
    __syncthreads();
    if (tid < 128) atomicAdd(&g_colsum[j0 + tid], colred[tid]);
}

// ================= reconstruct GEMM: fp16 mma, single-sync cp.async pipeline =================
__global__ __launch_bounds__(256, 2) void recon_mma(float* __restrict__ out) {
    extern __shared__ char smem[];
    uint32_t sb = smem_u32(smem);
    float* ds = (float*)smem;
    int tid = threadIdx.x, lane = tid & 31, w = tid >> 5;
    int n = blockIdx.z, hw0 = blockIdx.x * 128, c0 = blockIdx.y * 128;
    int wm = (w & 3) * 32, wn = (w >> 2) * 64;

    if (tid < 128) ds[tid] = g_dinv[n * HW + hw0 + tid];

    float acc[2][8][4];
#pragma unroll
    for (int a = 0; a < 2; ++a)
#pragma unroll
        for (int b = 0; b < 8; ++b)
#pragma unroll
            for (int c = 0; c < 4; ++c) acc[a][b][c] = 0.0f;

    int crow = tid >> 1, chalf = tid & 1;
    const uint4* aF = (const uint4*)(g_Sck + ((size_t)n * CD + c0 + crow) * KA);
    const uint4* bF = (const uint4*)(g_A0 + ((size_t)(n * HW + hw0 + crow)) * KA);

    auto issue = [&](int ch, int st) {
        uint32_t base = sb + G_STG(st);
#pragma unroll
        for (int q = 0; q < 4; ++q) {
            int unit = chalf * 4 + q;
            uint32_t off = swz((uint32_t)(crow * 128 + unit * 16));
            int gi = ch * 8 + unit;
            CPA16(base + off, aF + gi);
            CPA16(base + G_BF + off, bF + gi);
        }
    };

    issue(0, 0); CP_COMMIT();
#pragma unroll 1
    for (int ch = 0; ch < 8; ++ch) {
        CP_WAIT0();
        __syncthreads();
        if (ch + 1 < 8) { issue(ch + 1, (ch + 1) & 1); CP_COMMIT(); }
        uint32_t tb = sb + G_STG(ch & 1);
#pragma unroll
        for (int s = 0; s < 4; ++s) {
            uint32_t af[2][4];
#pragma unroll
            for (int mt = 0; mt < 2; ++mt)
                ldm4(afrag_addr(tb, wm + mt * 16, s, lane), af[mt]);
#pragma unroll
            for (int ng = 0; ng < 4; ++ng) {
                uint32_t bf[4];
                ldm4(bfrag_addr(tb + G_BF, wn + ng * 16, s, lane), bf);
                mma_hf(acc[0][2*ng],   af[0], bf[0], bf[1]);
                mma_hf(acc[1][2*ng],   af[1], bf[0], bf[1]);
                mma_hf(acc[0][2*ng+1], af[0], bf[2], bf[3]);
                mma_hf(acc[1][2*ng+1], af[1], bf[2], bf[3]);
            }
        }
    }

#pragma unroll
    for (int mt = 0; mt < 2; ++mt) {
        int c = c0 + wm + mt * 16 + (lane >> 2);
        int nl = wn + (lane & 3) * 2;
        float* o0 = out + ((size_t)n * CD + c) * HW + hw0 + nl;
        float* o1 = out + ((size_t)n * CD + c + 8) * HW + hw0 + nl;
#pragma unroll
    for (int nt = 0; nt < 8; ++nt) {
            float rx = ds[nl + nt * 8], ry = ds[nl + nt * 8 + 1];
            *(float2*)(o0 + nt * 8) = make_float2(acc[mt][nt][0] * rx, acc[mt][nt][1] * ry);
            *(float2*)(o1 + nt * 8) = make_float2(acc[mt][nt][2] * rx, acc[mt][nt][3] * ry);
        }
    }
}

// ----------------------------------------------------------------
extern "C" void kernel_launch(void* const* d_in, const int* in_sizes, int n_in,
                              void* d_out, int out_size) {
    const float* x = (const float*)d_in[0];
    const int* idx = (const int*)d_in[1];
    float* out = (float*)d_out;

    cudaFuncSetAttribute(score_mma, cudaFuncAttributeMaxDynamicSharedMemorySize, G_SMEM);
    cudaFuncSetAttribute(recon_mma, cudaFuncAttributeMaxDynamicSharedMemorySize, G_SMEM);
    cudaFuncSetAttribute(sk_pass, cudaFuncAttributeMaxDynamicSharedMemorySize, SK4_SMEM);
    cudaFuncSetAttribute(prep_recon, cudaFuncAttributeMaxDynamicSharedMemorySize, SK4_SMEM);

    xtn_kernel<<<dim3(HW / 32, NB), 256>>>(x);          // norm + transpose + colsum zero
    gather_both<<<dim3(KA / 128, CD / 32, NB), 256>>>(x, idx);

    score_mma<<<dim3(HW / 128, KA / 128, NB), 256, G_SMEM>>>();   // A0(fp16) + colsum0

    recip_kernel<<<1, KA>>>();                       // c1 (max-normalized)
    for (int it = 0; it < 3; ++it) {
        sk_pass<<<ROWS / 64, 256, SK4_SMEM>>>();
        recip_kernel<<<1, KA>>>();                   // c2, c3, c4
    }
    prep_recon<<<1024 + (NB * CD * KA) / 256, 256, SK4_SMEM>>>();  // dinv + S*c
    recon_mma<<<dim3(HW / 128, CD / 128, NB), 256, G_SMEM>>>(out);
}

// round 16
// speedup vs baseline: 1.0406x; 1.0406x over previous
#include <cuda_runtime.h>
#include <cuda_fp16.h>
#include <cstdint>

#define NB 16
#define CD 256
#define HW 4096
#define KA 512
#define ROWS (NB*HW)   // 65536

// ---------------- scratch (__device__ globals; no allocations) ----------------
__device__ __align__(16) __half g_A0[(size_t)ROWS * KA];             // 64 MB (fp16)
__device__ __align__(16) __half g_Xf[(size_t)ROWS * CD];             // X^T*invnorm fp16 [n][hw][c]
__device__ __align__(16) __half g_Sfj[(size_t)NB*KA*CD];             // S fp16 [n][j][c]
__device__ __align__(16) float  g_Scf[(size_t)NB*CD*KA];             // S fp32 [n][c][j]
__device__ __align__(16) __half g_Sck[(size_t)NB*CD*KA];             // S*c fp16 [n][c][j]
__device__ float g_invnorm[ROWS];
__device__ float g_colsum[KA];
__device__ float g_cvec[KA];

// ---------------- helpers ----------------
__device__ __forceinline__ uint32_t smem_u32(const void* p) {
    uint32_t a;
    asm("{ .reg .u64 t; cvta.to.shared.u64 t, %1; cvt.u32.u64 %0, t; }" : "=r"(a) : "l"(p));
    return a;
}
__device__ __forceinline__ uint32_t swz(uint32_t o) { return o ^ ((o >> 3) & 0x70); }
__device__ __forceinline__ void ldm4(uint32_t addr, uint32_t r[4]) {
    asm volatile("ldmatrix.sync.aligned.m8n8.x4.shared.b16 {%0,%1,%2,%3}, [%4];"
        : "=r"(r[0]), "=r"(r[1]), "=r"(r[2]), "=r"(r[3]) : "r"(addr));
}
__device__ __forceinline__ void mma_hf(float c[4], const uint32_t a[4],
                                       uint32_t b0, uint32_t b1) {
    asm volatile("mma.sync.aligned.m16n8k16.row.col.f32.f16.f16.f32 "
        "{%0,%1,%2,%3}, {%4,%5,%6,%7}, {%8,%9}, {%0,%1,%2,%3};"
        : "+f"(c[0]), "+f"(c[1]), "+f"(c[2]), "+f"(c[3])
        : "r"(a[0]), "r"(a[1]), "r"(a[2]), "r"(a[3]), "r"(b0), "r"(b1));
}
__device__ __forceinline__ uint32_t afrag_addr(uint32_t base, int mbase, int s, int lane) {
    int row = mbase + (lane & 7) + ((lane >> 3) & 1) * 8;
    int unit = 2 * s + (lane >> 4);
    return base + swz((uint32_t)(row * 128 + unit * 16));
}
__device__ __forceinline__ uint32_t bfrag_addr(uint32_t base, int nbase, int s, int lane) {
    int row = nbase + (lane & 7) + ((lane >> 4) & 1) * 8;
    int unit = 2 * s + ((lane >> 3) & 1);
    return base + swz((uint32_t)(row * 128 + unit * 16));
}
#define CPA16(s, g) asm volatile("cp.async.cg.shared.global [%0], [%1], 16;" :: "r"(s), "l"(g))
#define CP_COMMIT() asm volatile("cp.async.commit_group;" ::: "memory")
#define CP_WAIT0()  asm volatile("cp.async.wait_group 0;" ::: "memory")

// GEMM SMEM: red 512B @0 | cs 2KB @512 | stage s @4096+s*32768: AF +0, BF +16384
#define G_STG(s) (4096 + (s) * 32768)
#define G_BF 16384
#define G_SMEM (4096 + 65536)   // 69632; 2 CTA/SM

// ---------------- small kernels (round-10 verbatim) ----------------

__global__ __launch_bounds__(256) void xtn_kernel(const float* __restrict__ x) {
    __shared__ float t[256][33];
    __shared__ float ps[8][32];
    __shared__ float inv[32];
    int n = blockIdx.y, hw0 = blockIdx.x * 32;
    int tid = threadIdx.x;
    if (blockIdx.x == 0 && blockIdx.y == 0) {
        g_colsum[tid] = 0.0f; g_colsum[tid + 256] = 0.0f;
    }
    int tx = tid & 31, ty = tid >> 5;
    const float* p = x + (size_t)n * CD * HW + hw0 + tx;
#pragma unroll
    for (int cc = 0; cc < 32; ++cc) {
        int c = cc * 8 + ty;
        t[c][tx] = p[(size_t)c * HW];
    }
    __syncthreads();
    float s = 0.f;
#pragma unroll
    for (int k = 0; k < 32; ++k) {
        float v = t[ty * 32 + k][tx];
        s = fmaf(v, v, s);
    }
    ps[ty][tx] = s;
    __syncthreads();
    if (ty == 0) {
        float a = 0.f;
#pragma unroll
        for (int k = 0; k < 8; ++k) a += ps[k][tx];
        float invn = 1.0f / fmaxf(sqrtf(a), 1e-12f);
        inv[tx] = invn;
        g_invnorm[n * HW + hw0 + tx] = invn;
    }
    __syncthreads();
    int c2 = tid & 127, hwp = tid >> 7;
#pragma unroll
    for (int it = 0; it < 16; ++it) {
        int hw = it * 2 + hwp;
        float iv = inv[hw];
        float v0 = t[c2 * 2][hw] * iv;
        float v1 = t[c2 * 2 + 1][hw] * iv;
        *(__half2*)(&g_Xf[((size_t)n * HW + hw0 + hw) * CD + c2 * 2]) =
            __halves2half2(__float2half(v0), __float2half(v1));
    }
}

__global__ __launch_bounds__(256) void gather_both(const float* __restrict__ x,
                                                   const int* __restrict__ idx) {
    __shared__ float t[32][129];
    __shared__ int   pos_s[128];
    __shared__ float inv_s[128];
    int n = blockIdx.z, c0 = blockIdx.y * 32, j0 = blockIdx.x * 128;
    int tid = threadIdx.x;
    if (tid < 128) {
        int p = idx[j0 + tid];
        pos_s[tid] = p;
        inv_s[tid] = g_invnorm[n * HW + p];
    }
    __syncthreads();
#pragma unroll
    for (int it = 0; it < 16; ++it) {
        int e = tid + it * 256;
        int c = e >> 7, j = e & 127;
        float v = x[((size_t)(n * CD + c0 + c)) * HW + pos_s[j]] * inv_s[j];
        g_Scf[((size_t)(n * CD + c0 + c)) * KA + j0 + j] = v;
        t[c][j] = v;
    }
    __syncthreads();
#pragma unroll
    for (int it = 0; it < 16; ++it) {
        int e = tid + it * 256;
        int j = e >> 5, c = e & 31;
        g_Sfj[((size_t)(n * KA + j0 + j)) * CD + c0 + c] = __float2half(t[c][j]);
    }
}

__global__ void recip_kernel() {
    __shared__ float sm[KA];
    int j = threadIdx.x;
    float c = 1.0f / fmaxf(g_colsum[j], 1e-30f);
    sm[j] = c;
    __syncthreads();
    for (int s = 256; s > 0; s >>= 1) {
        if (j < s) sm[j] = fmaxf(sm[j], sm[j + s]);
        __syncthreads();
    }
    g_cvec[j] = c / sm[0];
    g_colsum[j] = 0.0f;
}

// fused Sinkhorn pass (round-10 version, grid ROWS/128)
__global__ __launch_bounds__(256) void sk_pass() {
    __shared__ float cred[KA];
    int tid = threadIdx.x;
    cred[tid] = 0.0f; cred[tid + 256] = 0.0f;
    __syncthreads();
    int warp = tid >> 5, lane = tid & 31;
    float cv[16];
#pragma unroll
    for (int e = 0; e < 8; ++e) { cv[e] = g_cvec[lane * 8 + e]; cv[8 + e] = g_cvec[256 + lane * 8 + e]; }
    float ca[16];
#pragma unroll
    for (int e = 0; e < 16; ++e) ca[e] = 0.0f;
    size_t rbase = (size_t)blockIdx.x * 128 + warp * 16;
    for (int t = 0; t < 16; ++t) {
        const uint4* row = (const uint4*)(g_A0 + (rbase + t) * KA);
        uint4 u0 = row[lane], u1 = row[lane + 32];
        float a[16];
        {
            const __half2* h0 = (const __half2*)&u0;
            const __half2* h1 = (const __half2*)&u1;
#pragma unroll
            for (int k = 0; k < 4; ++k) {
                float2 f0 = __half22float2(h0[k]);
                float2 f1 = __half22float2(h1[k]);
                a[2*k] = f0.x; a[2*k+1] = f0.y;
                a[8 + 2*k] = f1.x; a[8 + 2*k+1] = f1.y;
            }
        }
        float d = 0.0f;
#pragma unroll
        for (int e = 0; e < 16; ++e) d = fmaf(a[e], cv[e], d);
#pragma unroll
        for (int s = 16; s > 0; s >>= 1) d += __shfl_xor_sync(0xffffffffu, d, s);
        float r = 1.0f / fmaxf(d, 1e-30f);
#pragma unroll
        for (int e = 0; e < 16; ++e) ca[e] = fmaf(r, a[e], ca[e]);
    }
#pragma unroll
    for (int e = 0; e < 8; ++e) {
        atomicAdd(&cred[lane * 8 + e], ca[e]);
        atomicAdd(&cred[256 + lane * 8 + e], ca[8 + e]);
    }
    __syncthreads();
    atomicAdd(&g_colsum[tid], cred[tid]);
    atomicAdd(&g_colsum[tid + 256], cred[tid + 256]);
}

// S' = fp16(S_float * cvec)  [n][c][j]   (dinv now fused into recon)
__global__ __launch_bounds__(256) void scale_s_kernel() {
    int t = blockIdx.x * blockDim.x + threadIdx.x;
    int j = t & (KA - 1);
    g_Sck[t] = __float2half(g_Scf[t] * g_cvec[j]);
}

// ================= score GEMM (round-10 verbatim) =================
__global__ __launch_bounds__(256, 2) void score_mma() {
    extern __shared__ char smem[];
    uint32_t sb = smem_u32(smem);
    float* colred = (float*)smem;
    int tid = threadIdx.x, lane = tid & 31, w = tid >> 5;
    int n = blockIdx.z, hw0 = blockIdx.x * 128, j0 = blockIdx.y * 128;
    int wm = (w & 3) * 32, wn = (w >> 2) * 64;

    float acc[2][8][4];
#pragma unroll
    for (int a = 0; a < 2; ++a)
#pragma unroll
        for (int b = 0; b < 8; ++b)
#pragma unroll
            for (int c = 0; c < 4; ++c) acc[a][b][c] = 0.0f;

    int crow = tid >> 1, chalf = tid & 1;
    const uint4* aF = (const uint4*)(g_Xf + ((size_t)n * HW + hw0 + crow) * CD);
    const uint4* bF = (const uint4*)(g_Sfj + ((size_t)n * KA + j0 + crow) * CD);

    auto issue = [&](int ch, int st) {
        uint32_t base = sb + G_STG(st);
#pragma unroll
        for (int q = 0; q < 4; ++q) {
            int unit = chalf * 4 + q;
            uint32_t off = swz((uint32_t)(crow * 128 + unit * 16));
            int gi = ch * 8 + unit;
            CPA16(base + off, aF + gi);
            CPA16(base + G_BF + off, bF + gi);
        }
    };

    issue(0, 0); CP_COMMIT();
#pragma unroll 1
    for (int ch = 0; ch < 4; ++ch) {
        CP_WAIT0();
        __syncthreads();
        if (ch + 1 < 4) { issue(ch + 1, (ch + 1) & 1); CP_COMMIT(); }
        uint32_t tb = sb + G_STG(ch & 1);
#pragma unroll
        for (int s = 0; s < 4; ++s) {
            uint32_t af[2][4];
#pragma unroll
            for (int mt = 0; mt < 2; ++mt)
                ldm4(afrag_addr(tb, wm + mt * 16, s, lane), af[mt]);
#pragma unroll
            for (int ng = 0; ng < 4; ++ng) {
                uint32_t bf[4];
                ldm4(bfrag_addr(tb + G_BF, wn + ng * 16, s, lane), bf);
                mma_hf(acc[0][2*ng],   af[0], bf[0], bf[1]);
                mma_hf(acc[1][2*ng],   af[1], bf[0], bf[1]);
                mma_hf(acc[0][2*ng+1], af[0], bf[2], bf[3]);
                mma_hf(acc[1][2*ng+1], af[1], bf[2], bf[3]);
            }
        }
    }

    __syncthreads();
    if (tid < 128) colred[tid] = 0.0f;
    __syncthreads();
    const float sc = 1.0f / 0.3f;
    float colp[16];
#pragma unroll
    for (int e = 0; e < 16; ++e) colp[e] = 0.0f;
#pragma unroll
    for (int mt = 0; mt < 2; ++mt) {
        int i0 = n * HW + hw0 + wm + mt * 16 + (lane >> 2);
        int i1 = i0 + 8;
        __half* r0 = g_A0 + (size_t)i0 * KA + j0 + wn + (lane & 3) * 2;
        __half* r1 = g_A0 + (size_t)i1 * KA + j0 + wn + (lane & 3) * 2;
#pragma unroll
        for (int nt = 0; nt < 8; ++nt) {
            __half h0 = __float2half(__expf(acc[mt][nt][0] * sc));
            __half h1 = __float2half(__expf(acc[mt][nt][1] * sc));
            __half h2 = __float2half(__expf(acc[mt][nt][2] * sc));
            __half h3 = __float2half(__expf(acc[mt][nt][3] * sc));
            *(__half2*)(r0 + nt * 8) = __halves2half2(h0, h1);
            *(__half2*)(r1 + nt * 8) = __halves2half2(h2, h3);
            colp[nt * 2]     += __half2float(h0) + __half2float(h2);
            colp[nt * 2 + 1] += __half2float(h1) + __half2float(h3);
        }
    }
#pragma unroll
    for (int nt = 0; nt < 8; ++nt) {
        int cl = wn + (lane & 3) * 2 + nt * 8;
        atomicAdd(&colred[cl], colp[nt * 2]);
        atomicAdd(&colred[cl + 1], colp[nt * 2 + 1]);
    }
    __syncthreads();
    if (tid < 128) atomicAdd(&g_colsum[j0 + tid], colred[tid]);
}

// ================= reconstruct GEMM: fused d row-sum (round-4/6 pattern) =================
__global__ __launch_bounds__(256, 2) void recon_mma(float* __restrict__ out) {
    extern __shared__ char smem[];
    uint32_t sb = smem_u32(smem);
    float* red = (float*)smem;            // 128 floats: d accumulator
    float* cs  = (float*)(smem + 512);    // 512 floats: cvec copy
    int tid = threadIdx.x, lane = tid & 31, w = tid >> 5;
    int n = blockIdx.z, hw0 = blockIdx.x * 128, c0 = blockIdx.y * 128;
    int wm = (w & 3) * 32, wn = (w >> 2) * 64;

    if (tid < 128) red[tid] = 0.0f;
    cs[tid] = g_cvec[tid];
    cs[256 + tid] = g_cvec[256 + tid];

    float acc[2][8][4];
#pragma unroll
    for (int a = 0; a < 2; ++a)
#pragma unroll
        for (int b = 0; b < 8; ++b)
#pragma unroll
            for (int c = 0; c < 4; ++c) acc[a][b][c] = 0.0f;

    int crow = tid >> 1, chalf = tid & 1;
    const uint4* aF = (const uint4*)(g_Sck + ((size_t)n * CD + c0 + crow) * KA);
    const uint4* bF = (const uint4*)(g_A0 + ((size_t)(n * HW + hw0 + crow)) * KA);

    auto issue = [&](int ch, int st) {
        uint32_t base = sb + G_STG(st);
#pragma unroll
        for (int q = 0; q < 4; ++q) {
            int unit = chalf * 4 + q;
            uint32_t off = swz((uint32_t)(crow * 128 + unit * 16));
            int gi = ch * 8 + unit;
            CPA16(base + off, aF + gi);
            CPA16(base + G_BF + off, bF + gi);
        }
    };

    issue(0, 0); CP_COMMIT();
#pragma unroll 1
    for (int ch = 0; ch < 8; ++ch) {
        CP_WAIT0();
        __syncthreads();   // also orders red/cs init before first use
        if (ch + 1 < 8) { issue(ch + 1, (ch + 1) & 1); CP_COMMIT(); }
        uint32_t tb = sb + G_STG(ch & 1);
#pragma unroll
        for (int s = 0; s < 4; ++s) {
            uint32_t af[2][4];
#pragma unroll
            for (int mt = 0; mt < 2; ++mt)
                ldm4(afrag_addr(tb, wm + mt * 16, s, lane), af[mt]);
#pragma unroll
            for (int ng = 0; ng < 4; ++ng) {
                uint32_t bf[4];
                ldm4(bfrag_addr(tb + G_BF, wn + ng * 16, s, lane), bf);
                mma_hf(acc[0][2*ng],   af[0], bf[0], bf[1]);
                mma_hf(acc[1][2*ng],   af[1], bf[0], bf[1]);
                mma_hf(acc[0][2*ng+1], af[0], bf[2], bf[3]);
                mma_hf(acc[1][2*ng+1], af[1], bf[2], bf[3]);
            }
        }
        // fused d row-sum: this thread re-reads the 4 B units it loaded (row crow,
        // j range ch*64 + (chalf*4+q)*8 ..+7), dots with cs, accumulates into red.
        {
            char* bbase = smem + (size_t)(G_STG(ch & 1) + G_BF);
            float dp = 0.0f;
#pragma unroll
            for (int q = 0; q < 4; ++q) {
                int unit = chalf * 4 + q;
                uint4 u = *(const uint4*)(bbase + swz((uint32_t)(crow * 128 + unit * 16)));
                const __half2* hp = (const __half2*)&u;
                int jb = ch * 64 + unit * 8;
#pragma unroll
                for (int k = 0; k < 4; ++k) {
                    float2 f = __half22float2(hp[k]);
                    dp = fmaf(f.x, cs[jb + 2*k], dp);
                    dp = fmaf(f.y, cs[jb + 2*k + 1], dp);
                }
            }
            atomicAdd(&red[crow], dp);
        }
    }

    __syncthreads();
    if (tid < 128) red[tid] = 1.0f / fmaxf(red[tid], 1e-30f);
    __syncthreads();

#pragma unroll
    for (int mt = 0; mt < 2; ++mt) {
        int c = c0 + wm + mt * 16 + (lane >> 2);
        int nl = wn + (lane & 3) * 2;
        float* o0 = out + ((size_t)n * CD + c) * HW + hw0 + nl;
        float* o1 = out + ((size_t)n * CD + c + 8) * HW + hw0 + nl;
#pragma unroll
        for (int nt = 0; nt < 8; ++nt) {
            float rx = red[nl + nt * 8], ry = red[nl + nt * 8 + 1];
            *(float2*)(o0 + nt * 8) = make_float2(acc[mt][nt][0] * rx, acc[mt][nt][1] * ry);
            *(float2*)(o1 + nt * 8) = make_float2(acc[mt][nt][2] * rx, acc[mt][nt][3] * ry);
        }
    }
}

// ----------------------------------------------------------------
extern "C" void kernel_launch(void* const* d_in, const int* in_sizes, int n_in,
                              void* d_out, int out_size) {
    const float* x = (const float*)d_in[0];
    const int* idx = (const int*)d_in[1];
    float* out = (float*)d_out;

    cudaFuncSetAttribute(score_mma, cudaFuncAttributeMaxDynamicSharedMemorySize, G_SMEM);
    cudaFuncSetAttribute(recon_mma, cudaFuncAttributeMaxDynamicSharedMemorySize, G_SMEM);

    xtn_kernel<<<dim3(HW / 32, NB), 256>>>(x);          // norm + transpose + colsum zero
    gather_both<<<dim3(KA / 128, CD / 32, NB), 256>>>(x, idx);

    score_mma<<<dim3(HW / 128, KA / 128, NB), 256, G_SMEM>>>();   // A0(fp16) + colsum0

    recip_kernel<<<1, KA>>>();                       // c1 (max-normalized)
    for (int it = 0; it < 3; ++it) {
        sk_pass<<<ROWS / 128, 256>>>();
        recip_kernel<<<1, KA>>>();                   // c2, c3, c4
    }
    scale_s_kernel<<<(NB * CD * KA) / 256, 256>>>(); // S' = S * c4 (fp16)
    recon_mma<<<dim3(HW / 128, CD / 128, NB), 256, G_SMEM>>>(out);  // dinv fused
}